// round 13
// baseline (speedup 1.0000x reference)
#include <cuda_runtime.h>
#include <math.h>

#define N_G   1024
#define SCALE 1.0f
#define DXC   (2.0f / 31.0f)
#define QCUT  60.0f                // dropped terms < e^-30 of dominant: negligible
#define CANDCAP 384
#define GRID_TOTAL 512

__device__ float d_img[N_G * 75];  // (N, 3, 5, 5): c*25 + kx*5 + ky
__device__ unsigned g_arrive;      // zero-init; reset at end of every run
__device__ unsigned g_depart;

__device__ __forceinline__ float tanha(float x) {
    float y;
    asm("tanh.approx.f32 %0, %1;" : "=f"(y) : "f"(x));
    return y;
}

// ---- dynamic smem layout (float offsets), all regions 16B-aligned ----
// Phase B (written AFTER the grid barrier):
#define OFF_IMG   0        // imgT[75][8] = 600
#define OFF_SHT   600      // shT[80][8] = 640
#define OFF_SH2T  1240     // sh2T[80][8] = 640
#define OFF_PP    1880     // 3 chunks x 640 = 1920
#define OFF_HP    3800     // 64
#define OFF_PRMT  3864     // prmT[6][8] = 48
#define SMEM_FLTS 3920     // 15680 B -> >=8 blocks/SM capacity; need 4

// Phase A scratch aliases the same region (used only BEFORE the barrier):
#define PA_CA    0         // 384 float4 = 1536
#define PA_CB    1536      // 1536
#define PA_MISC  3072      // wcnt8+wbase8+total
#define PA_PUS   3092      // 100
#define PA_PPD   3192      // 100

__global__ void __launch_bounds__(256) k_all(
    const float* __restrict__ means,  const float* __restrict__ u,
    const float* __restrict__ scaling,const float* __restrict__ transform,
    const float* __restrict__ conv_w, const float* __restrict__ conv_b,
    const float* __restrict__ emb_w,  const float* __restrict__ emb_b,
    const float* __restrict__ lin1_w, const float* __restrict__ lin1_b,
    const float* __restrict__ sol_w,  const float* __restrict__ sol_b,
    const float* __restrict__ tr_w,   const float* __restrict__ tr_b,
    const float* __restrict__ sc_w,   const float* __restrict__ sc_b,
    const float* __restrict__ tf_w,   const float* __restrict__ tf_b,
    float* __restrict__ out)
{
    extern __shared__ float sm[];
    const int b    = blockIdx.x;
    const int tid  = threadIdx.x;
    const int w    = tid >> 5;
    const int lane = tid & 31;

    // =================== PHASE A (even blocks): gaussians [(b>>1)*4, +4) =====
    if ((b & 1) == 0) {
        float4* cA = (float4*)(sm + PA_CA);
        float4* cB = (float4*)(sm + PA_CB);
        int* s_wcnt  = (int*)(sm + PA_MISC);
        int* s_wbase = (int*)(sm + PA_MISC + 8);
        int* s_total = (int*)(sm + PA_MISC + 16);
        float* pus = sm + PA_PUS;
        float* ppd = sm + PA_PPD;

        if (tid == 0) *s_total = 0;
        __syncthreads();

        const int i0 = (b >> 1) * 4;
        float bminx = 1e30f, bmaxx = -1e30f, bminy = 1e30f, bmaxy = -1e30f;
        #pragma unroll
        for (int g = 0; g < 4; ++g) {
            float mx = means[2 * (i0 + g)], my = means[2 * (i0 + g) + 1];
            bminx = fminf(bminx, mx); bmaxx = fmaxf(bmaxx, mx);
            bminy = fminf(bminy, my); bmaxy = fmaxf(bmaxy, my);
        }
        bminx -= 2.0f * DXC; bmaxx += 2.0f * DXC;
        bminy -= 2.0f * DXC; bmaxy += 2.0f * DXC;

        for (int c = 0; c < N_G / 256; ++c) {
            int j = c * 256 + tid;
            float mx = means[2 * j], my = means[2 * j + 1];
            float s0 = scaling[2 * j], s1 = scaling[2 * j + 1], t = transform[j];
            float A = s0 * s0, B = s0 * t, C = t * t + s1 * s1;
            float inv = 1.0f / (A * C - B * B);
            float ca =  C * inv, cb = -B * inv, cc = A * inv;
            float h = 0.5f * (A + C);
            float r = sqrtf(0.25f * (A - C) * (A - C) + B * B);
            float r2max = QCUT * (h + r);
            float ddx = fmaxf(fmaxf(bminx - mx, mx - bmaxx), 0.0f);
            float ddy = fmaxf(fmaxf(bminy - my, my - bmaxy), 0.0f);
            bool pred = (ddx * ddx + ddy * ddy) <= r2max;
            unsigned bm = __ballot_sync(0xffffffffu, pred);
            if (lane == 0) s_wcnt[w] = __popc(bm);
            __syncthreads();
            if (tid == 0) {
                int acc = *s_total;
                for (int w2 = 0; w2 < 8; ++w2) { s_wbase[w2] = acc; acc += s_wcnt[w2]; }
                *s_total = acc;
            }
            __syncthreads();
            if (pred) {
                int idx = s_wbase[w] + __popc(bm & ((1u << lane) - 1u));
                if (idx < CANDCAP) {
                    cA[idx] = make_float4(mx, my, r2max, u[j]);
                    cB[idx] = make_float4(ca, cb, cc, ca + cc);
                }
            }
            __syncthreads();
        }
        int cnt = *s_total;
        if (cnt > CANDCAP) cnt = CANDCAP;

        // evaluate 100 samples on 200 threads (2/sample, even/odd split)
        float us = 0.0f, pd = 0.0f;
        float sx = 0.0f, sy = 0.0f;
        int   sl = 0;
        if (tid < 200) {
            int half = tid / 100;
            sl = tid - half * 100;
            const int i  = i0 + sl / 25;
            const int k  = sl % 25;
            const int kx = k / 5, ky = k % 5;
            sx = means[2 * i]     + (float)(kx - 2) * DXC;
            sy = means[2 * i + 1] + (float)(ky - 2) * DXC;
            for (int t2 = half; t2 < cnt; t2 += 2) {
                float4 A  = cA[t2];
                float4 Bv = cB[t2];
                float dx = sx - A.x;
                float dy = sy - A.y;
                float Cd0 = Bv.x * dx + Bv.y * dy;
                float Cd1 = Bv.y * dx + Bv.z * dy;
                float q   = dx * Cd0 + dy * Cd1;
                float wv  = __expf(-0.5f * q) * A.w;
                us += wv;
                pd += wv * (Cd0 * Cd0 + Cd1 * Cd1 - Bv.w);
            }
            if (half == 1) { pus[sl] = us; ppd[sl] = pd; }
        }
        __syncthreads();
        if (tid < 100) {
            us += pus[sl];
            pd += ppd[sl];
            const int i = i0 + sl / 25;
            const int k = sl % 25;
            float maskv = (fabsf(sx) < SCALE && fabsf(sy) < SCALE) ? 1.0f : 0.0f;
            d_img[i * 75 +  0 + k] = us;
            d_img[i * 75 + 25 + k] = pd;
            d_img[i * 75 + 50 + k] = maskv;
        }
    }

    // =================== GRID BARRIER (512 blocks co-resident) ===============
    __threadfence();
    __syncthreads();
    if (tid == 0) {
        atomicAdd(&g_arrive, 1u);
        while (atomicAdd(&g_arrive, 0u) < GRID_TOTAL) { }
    }
    __syncthreads();

    // =================== PHASE B: one net x 8 gaussians per block ============
    const int m  = b & 3;
    const int g0 = (b >> 2) * 8;
    const int od = (m == 1 || m == 2) ? 2 : 1;

    float* imgT = sm + OFF_IMG;    // [kk*8 + g]
    float* shT  = sm + OFF_SHT;    // [row*8 + g]
    float* sh2T = sm + OFF_SH2T;   // [q*8 + g]
    float* pp   = sm + OFF_PP;     // 3 x [q*8 + g]
    float* hpart= sm + OFF_HP;
    float* prmT = sm + OFF_PRMT;   // [p*8 + g]

    const float* cw = conv_w + m * 3750;
    const float* ew = emb_w  + m * 180;
    const float* lw = lin1_w + m * 6400;
    const float* hw; const float* hb;
    if      (m == 0) { hw = sol_w; hb = sol_b; }
    else if (m == 1) { hw = tr_w;  hb = tr_b;  }
    else if (m == 2) { hw = sc_w;  hb = sc_b;  }
    else             { hw = tf_w;  hb = tf_b;  }

    // imgT + params
    for (int idx = tid; idx < 600; idx += 256) {
        int g = idx / 75, kk = idx - g * 75;
        imgT[kk * 8 + g] = d_img[(g0 + g) * 75 + kk];
    }
    if (tid < 48) {
        int p = tid >> 3, g = tid & 7;
        int i = g0 + g;
        float v;
        if      (p == 0) v = means[2 * i];
        else if (p == 1) v = means[2 * i + 1];
        else if (p == 2) v = u[i];
        else if (p == 3) v = scaling[2 * i];
        else if (p == 4) v = scaling[2 * i + 1];
        else             v = transform[i];
        prmT[p * 8 + g] = v;
    }
    __syncthreads();

    // ---- stage 1: conv (tid<100: 1o x 4g) + emb (tid 128..187: 1q x 4g) ----
    if (tid < 100) {
        int o  = tid >> 1;
        int gb = (tid & 1) * 4;
        float bias = __ldg(conv_b + m * 50 + o);
        float a0 = bias, a1 = bias, a2 = bias, a3 = bias;
        const float* wr = cw + o * 75;
        #pragma unroll 5
        for (int kk = 0; kk < 75; ++kk) {
            float wv = __ldg(wr + kk);
            float4 v = *(const float4*)&imgT[kk * 8 + gb];
            a0 = fmaf(wv, v.x, a0); a1 = fmaf(wv, v.y, a1);
            a2 = fmaf(wv, v.z, a2); a3 = fmaf(wv, v.w, a3);
        }
        *(float4*)&shT[o * 8 + gb] = make_float4(tanha(a0), tanha(a1), tanha(a2), tanha(a3));
    } else if (tid >= 128 && tid < 188) {
        int et = tid - 128;
        int q  = et >> 1;
        int gb = (et & 1) * 4;
        float bias = __ldg(emb_b + m * 30 + q);
        float a0 = bias, a1 = bias, a2 = bias, a3 = bias;
        #pragma unroll
        for (int p = 0; p < 6; ++p) {
            float wv = __ldg(ew + p * 30 + q);
            float4 pv = *(const float4*)&prmT[p * 8 + gb];
            a0 = fmaf(wv, pv.x, a0); a1 = fmaf(wv, pv.y, a1);
            a2 = fmaf(wv, pv.z, a2); a3 = fmaf(wv, pv.w, a3);
        }
        *(float4*)&shT[(50 + q) * 8 + gb] = make_float4(tanha(a0), tanha(a1), tanha(a2), tanha(a3));
    }
    __syncthreads();

    // ---- stage 2: 80x80, 4q x 4g x 4 p-chunks = 160 tasks ----
    {
        const bool active = (tid < 160);
        int chunk = 0, q0 = 0, gb = 0;
        float acc[4][4];
        #pragma unroll
        for (int a = 0; a < 4; ++a)
            #pragma unroll
            for (int bb = 0; bb < 4; ++bb) acc[a][bb] = 0.0f;
        if (active) {
            chunk = tid / 40;            // 0..3
            int r = tid - chunk * 40;    // 0..39
            q0 = (r >> 1) * 4;           // 0..76
            gb = (r & 1) * 4;
            int pbase = chunk * 20;
            #pragma unroll 4
            for (int j = 0; j < 20; ++j) {
                int p = pbase + j;
                float4 wv = __ldg((const float4*)(lw + p * 80 + q0));
                float4 hv = *(const float4*)&shT[p * 8 + gb];
                acc[0][0] = fmaf(wv.x, hv.x, acc[0][0]); acc[0][1] = fmaf(wv.x, hv.y, acc[0][1]);
                acc[0][2] = fmaf(wv.x, hv.z, acc[0][2]); acc[0][3] = fmaf(wv.x, hv.w, acc[0][3]);
                acc[1][0] = fmaf(wv.y, hv.x, acc[1][0]); acc[1][1] = fmaf(wv.y, hv.y, acc[1][1]);
                acc[1][2] = fmaf(wv.y, hv.z, acc[1][2]); acc[1][3] = fmaf(wv.y, hv.w, acc[1][3]);
                acc[2][0] = fmaf(wv.z, hv.x, acc[2][0]); acc[2][1] = fmaf(wv.z, hv.y, acc[2][1]);
                acc[2][2] = fmaf(wv.z, hv.z, acc[2][2]); acc[2][3] = fmaf(wv.z, hv.w, acc[2][3]);
                acc[3][0] = fmaf(wv.w, hv.x, acc[3][0]); acc[3][1] = fmaf(wv.w, hv.y, acc[3][1]);
                acc[3][2] = fmaf(wv.w, hv.z, acc[3][2]); acc[3][3] = fmaf(wv.w, hv.w, acc[3][3]);
            }
        }
        if (active && chunk < 3) {
            float* dst = pp + chunk * 640;
            #pragma unroll
            for (int a = 0; a < 4; ++a)
                #pragma unroll
                for (int bb = 0; bb < 4; ++bb)
                    dst[(q0 + a) * 8 + gb + bb] = acc[a][bb];
        }
        __syncthreads();
        if (active && chunk == 3) {
            #pragma unroll
            for (int a = 0; a < 4; ++a) {
                float bl = __ldg(lin1_b + m * 80 + q0 + a);
                #pragma unroll
                for (int bb = 0; bb < 4; ++bb) {
                    int off = (q0 + a) * 8 + gb + bb;
                    sh2T[off] = tanha(bl + acc[a][bb] + pp[off] + pp[640 + off] + pp[1280 + off]);
                }
            }
        }
    }
    __syncthreads();

    // ---- stage 3: head, 4 p-chunks x od x 8g ----
    if (tid < od * 32) {
        int g = tid & 7;
        int r = tid >> 3;
        int d = r % od;
        int chunk = r / od;             // 0..3
        int pbase = chunk * 20;
        float acc = 0.0f;
        #pragma unroll 5
        for (int p = 0; p < 20; ++p)
            acc = fmaf(sh2T[(pbase + p) * 8 + g], __ldg(hw + (pbase + p) * od + d), acc);
        hpart[(chunk * od + d) * 8 + g] = acc;
    }
    __syncthreads();
    if (tid < od * 8) {
        int g = tid & 7;
        int d = tid >> 3;
        float acc = __ldg(hb + d);
        #pragma unroll
        for (int c = 0; c < 4; ++c) acc += hpart[(c * od + d) * 8 + g];
        int i = g0 + g;
        if      (m == 0) out[i * 6 + 0]     = prmT[2 * 8 + g]       + acc;
        else if (m == 1) out[i * 6 + 1 + d] = prmT[d * 8 + g]       + acc;
        else if (m == 2) out[i * 6 + 3 + d] = prmT[(3 + d) * 8 + g] * __expf(acc);
        else             out[i * 6 + 5]     = prmT[5 * 8 + g]       + acc;
    }

    // ---- barrier counter reset (last block out restores initial state) ----
    __syncthreads();
    if (tid == 0) {
        unsigned d = atomicAdd(&g_depart, 1u) + 1u;
        if (d == GRID_TOTAL) { g_arrive = 0u; g_depart = 0u; __threadfence(); }
    }
}

// ---------------------------------------------------------------------------
extern "C" void kernel_launch(void* const* d_in, const int* in_sizes, int n_in,
                              void* d_out, int out_size)
{
    const float* means     = (const float*)d_in[0];
    const float* u         = (const float*)d_in[1];
    const float* scaling   = (const float*)d_in[2];
    const float* transform = (const float*)d_in[3];
    const float* conv_w    = (const float*)d_in[4];
    const float* conv_b    = (const float*)d_in[5];
    const float* emb_w     = (const float*)d_in[6];
    const float* emb_b     = (const float*)d_in[7];
    const float* lin1_w    = (const float*)d_in[8];
    const float* lin1_b    = (const float*)d_in[9];
    const float* sol_w     = (const float*)d_in[10];
    const float* sol_b     = (const float*)d_in[11];
    const float* tr_w      = (const float*)d_in[12];
    const float* tr_b      = (const float*)d_in[13];
    const float* sc_w      = (const float*)d_in[14];
    const float* sc_b      = (const float*)d_in[15];
    const float* tf_w      = (const float*)d_in[16];
    const float* tf_b      = (const float*)d_in[17];
    float* out             = (float*)d_out;

    static int smem_set = 0;
    if (!smem_set) {
        cudaFuncSetAttribute(k_all, cudaFuncAttributeMaxDynamicSharedMemorySize,
                             SMEM_FLTS * (int)sizeof(float));
        smem_set = 1;
    }

    k_all<<<GRID_TOTAL, 256, SMEM_FLTS * sizeof(float)>>>(
        means, u, scaling, transform,
        conv_w, conv_b, emb_w, emb_b, lin1_w, lin1_b,
        sol_w, sol_b, tr_w, tr_b, sc_w, sc_b, tf_w, tf_b, out);
}

// round 14
// speedup vs baseline: 1.1344x; 1.1344x over previous
#include <cuda_runtime.h>
#include <math.h>

#define N_G   1024
#define SCALE 1.0f
#define DXC   (2.0f / 31.0f)
#define QCUT  60.0f                // dropped terms < e^-30 of dominant: negligible
#define GPB   16                   // gaussians per block (phase B)
#define SEGCAP 64                  // per-warp candidate segment capacity
#define GRID_TOTAL 256

__device__ float d_img[N_G * 75];  // (N, 3, 5, 5): c*25 + kx*5 + ky
__device__ unsigned g_arrive;      // zero-init; reset at end of every run
__device__ unsigned g_depart;

__device__ __forceinline__ float tanha(float x) {
    float y;
    asm("tanh.approx.f32 %0, %1;" : "=f"(y) : "f"(x));
    return y;
}

// ---- dynamic smem layout (float offsets), all regions 16B-aligned ----
// Phase-B weight regions (loaded BEFORE the grid barrier):
#define OFF_SWC   0        // 3750 (+2)
#define OFF_SWE   3752     // 180
#define OFF_SWL   3932     // 6400
#define OFF_SBC   10332    // 50 (+2)
#define OFF_SBE   10384    // 30 (+2)
#define OFF_SBL   10416    // 80
#define OFF_SHW   10496    // 160
#define OFF_SHB   10656    // 2 (+2)
#define OFF_SPRM  10660    // 144
// Phase-B activation buffers (written only AFTER the barrier):
#define OFF_IMGT  10804    // 1200
#define OFF_SHT   12004    // 1280
#define OFF_SH2T  13284    // 1280
#define OFF_PP    14564    // 1280
#define OFF_PP2   15844    // 1280
#define OFF_HP    17124    // 128
#define SMEM_FLTS 17252    // 69008 B -> 3 blocks/SM, capacity 444 >= 256

// Phase-A scratch aliases into the activation region (pre-barrier only).
#define PA_CA    10804             // 8 segs * 64 float4 = 2048 floats
#define PA_CB    12852             // 2048 floats
#define PA_SCNT  14900             // 8
#define PA_PUS   14908             // 100
#define PA_PPD   15008             // 100

__global__ void __launch_bounds__(256) k_all(
    const float* __restrict__ means,  const float* __restrict__ u,
    const float* __restrict__ scaling,const float* __restrict__ transform,
    const float* __restrict__ conv_w, const float* __restrict__ conv_b,
    const float* __restrict__ emb_w,  const float* __restrict__ emb_b,
    const float* __restrict__ lin1_w, const float* __restrict__ lin1_b,
    const float* __restrict__ sol_w,  const float* __restrict__ sol_b,
    const float* __restrict__ tr_w,   const float* __restrict__ tr_b,
    const float* __restrict__ sc_w,   const float* __restrict__ sc_b,
    const float* __restrict__ tf_w,   const float* __restrict__ tf_b,
    float* __restrict__ out)
{
    extern __shared__ float sm[];
    const int b    = blockIdx.x;
    const int tid  = threadIdx.x;
    const int w    = tid >> 5;
    const int lane = tid & 31;

    const int m  = b & 3;               // network
    const int g0 = (b >> 2) * GPB;      // phase-B gaussian base
    const int od = (m == 1 || m == 2) ? 2 : 1;

    // ============ pre-barrier loads (overlap with phase A) ============
    {
        const float4* lw4 = (const float4*)(lin1_w + m * 6400);
        float4* sl4 = (float4*)(sm + OFF_SWL);
        for (int idx = tid; idx < 1600; idx += 256) sl4[idx] = lw4[idx];
        const float2* cw2 = (const float2*)(conv_w + m * 3750);
        float2* sc2 = (float2*)(sm + OFF_SWC);
        for (int idx = tid; idx < 1875; idx += 256) sc2[idx] = cw2[idx];
        const float2* ew2 = (const float2*)(emb_w + m * 180);
        float2* se2 = (float2*)(sm + OFF_SWE);
        if (tid < 90) se2[tid] = ew2[tid];
    }
    if (tid < 50) sm[OFF_SBC + tid] = conv_b[m * 50 + tid];
    if (tid >= 64 && tid < 94)  sm[OFF_SBE + tid - 64] = emb_b[m * 30 + (tid - 64)];
    if (tid >= 96 && tid < 176) sm[OFF_SBL + tid - 96] = lin1_b[m * 80 + (tid - 96)];
    {
        const float* hw; const float* hb;
        if      (m == 0) { hw = sol_w; hb = sol_b; }
        else if (m == 1) { hw = tr_w;  hb = tr_b;  }
        else if (m == 2) { hw = sc_w;  hb = sc_b;  }
        else             { hw = tf_w;  hb = tf_b;  }
        for (int idx = tid; idx < 80 * od; idx += 256) sm[OFF_SHW + idx] = hw[idx];
        if (tid < od) sm[OFF_SHB + tid] = hb[tid];
    }
    if (tid >= 224 && tid < 224 + GPB) {
        int g = tid - 224, i = g0 + g;
        sm[OFF_SPRM + g * 9 + 0] = means[2 * i];
        sm[OFF_SPRM + g * 9 + 1] = means[2 * i + 1];
        sm[OFF_SPRM + g * 9 + 2] = u[i];
        sm[OFF_SPRM + g * 9 + 3] = scaling[2 * i];
        sm[OFF_SPRM + g * 9 + 4] = scaling[2 * i + 1];
        sm[OFF_SPRM + g * 9 + 5] = transform[i];
    }

    // =================== PHASE A: sampling for gaussians [4b, 4b+4) ==========
    {
        float4* cA = (float4*)(sm + PA_CA);
        float4* cB = (float4*)(sm + PA_CB);
        int* s_scnt = (int*)(sm + PA_SCNT);
        float* pus = sm + PA_PUS;
        float* ppd = sm + PA_PPD;

        // tight bbox over this block's 4 gaussians (registers, no sync needed)
        const int i0 = b * 4;
        float bminx = 1e30f, bmaxx = -1e30f, bminy = 1e30f, bmaxy = -1e30f;
        #pragma unroll
        for (int g = 0; g < 4; ++g) {
            float mx = means[2 * (i0 + g)], my = means[2 * (i0 + g) + 1];
            bminx = fminf(bminx, mx); bmaxx = fmaxf(bmaxx, mx);
            bminy = fminf(bminy, my); bmaxy = fmaxf(bmaxy, my);
        }
        bminx -= 2.0f * DXC; bmaxx += 2.0f * DXC;
        bminy -= 2.0f * DXC; bmaxy += 2.0f * DXC;

        // per-warp segmented candidate scan: warp w owns j in [128w, 128w+128)
        // -> NO block-wide barriers; global j order preserved (segments ordered by w)
        {
            int cnt_w = 0;
            #pragma unroll
            for (int c = 0; c < 4; ++c) {
                int j = w * 128 + c * 32 + lane;
                float mx = means[2 * j], my = means[2 * j + 1];
                float s0 = scaling[2 * j], s1 = scaling[2 * j + 1], t = transform[j];
                float A = s0 * s0, B = s0 * t, C = t * t + s1 * s1;
                float inv = 1.0f / (A * C - B * B);
                float ca =  C * inv, cb = -B * inv, cc = A * inv;
                float h = 0.5f * (A + C);
                float r = sqrtf(0.25f * (A - C) * (A - C) + B * B);
                float r2max = QCUT * (h + r);
                float ddx = fmaxf(fmaxf(bminx - mx, mx - bmaxx), 0.0f);
                float ddy = fmaxf(fmaxf(bminy - my, my - bmaxy), 0.0f);
                bool pred = (ddx * ddx + ddy * ddy) <= r2max;
                unsigned bm = __ballot_sync(0xffffffffu, pred);
                if (pred) {
                    int idx = cnt_w + __popc(bm & ((1u << lane) - 1u));
                    if (idx < SEGCAP) {
                        cA[w * SEGCAP + idx] = make_float4(mx, my, r2max, u[j]);
                        cB[w * SEGCAP + idx] = make_float4(ca, cb, cc, ca + cc);
                    }
                }
                cnt_w += __popc(bm);
            }
            if (lane == 0) s_scnt[w] = (cnt_w > SEGCAP) ? SEGCAP : cnt_w;
        }
        __syncthreads();   // single barrier: segments + counts ready

        // evaluate 100 samples on 200 threads (2/sample), in-loop d2 prune
        float us = 0.0f, pd = 0.0f;
        float sx = 0.0f, sy = 0.0f;
        int   sl = 0;
        if (tid < 200) {
            int half = tid / 100;
            sl = tid - half * 100;
            const int i  = i0 + sl / 25;
            const int k  = sl % 25;
            const int kx = k / 5, ky = k % 5;
            sx = means[2 * i]     + (float)(kx - 2) * DXC;
            sy = means[2 * i + 1] + (float)(ky - 2) * DXC;
            #pragma unroll 1
            for (int sgm = 0; sgm < 8; ++sgm) {
                const int cn = s_scnt[sgm];
                const int base = sgm * SEGCAP;
                for (int t2 = half; t2 < cn; t2 += 2) {
                    float4 A = cA[base + t2];
                    float dx = sx - A.x;
                    float dy = sy - A.y;
                    float d2 = dx * dx + dy * dy;
                    if (d2 <= A.z) {
                        float4 Bv = cB[base + t2];
                        float Cd0 = Bv.x * dx + Bv.y * dy;
                        float Cd1 = Bv.y * dx + Bv.z * dy;
                        float q   = dx * Cd0 + dy * Cd1;
                        float wv  = __expf(-0.5f * q) * A.w;
                        us += wv;
                        pd += wv * (Cd0 * Cd0 + Cd1 * Cd1 - Bv.w);
                    }
                }
            }
            if (half == 1) { pus[sl] = us; ppd[sl] = pd; }
        }
        __syncthreads();
        if (tid < 100) {
            us += pus[sl];
            pd += ppd[sl];
            const int i = i0 + sl / 25;
            const int k = sl % 25;
            float maskv = (fabsf(sx) < SCALE && fabsf(sy) < SCALE) ? 1.0f : 0.0f;
            d_img[i * 75 +  0 + k] = us;
            d_img[i * 75 + 25 + k] = pd;
            d_img[i * 75 + 50 + k] = maskv;
        }
    }

    // ============ GRID BARRIER: one-shot atomic arrive, LOAD-based spin ======
    __threadfence();
    __syncthreads();
    if (tid == 0) {
        atomicAdd(&g_arrive, 1u);
        volatile unsigned* p = &g_arrive;
        while (*p < GRID_TOTAL) { }
    }
    __syncthreads();

    // =================== PHASE B: the 4 networks (R10 structure) =============
    float* swc  = sm + OFF_SWC;
    float* swe  = sm + OFF_SWE;
    float* swl  = sm + OFF_SWL;
    float* sbc  = sm + OFF_SBC;
    float* sbe  = sm + OFF_SBE;
    float* sbl  = sm + OFF_SBL;
    float* shw  = sm + OFF_SHW;
    float* shb  = sm + OFF_SHB;
    float* sprm = sm + OFF_SPRM;
    float* imgT = sm + OFF_IMGT;
    float* shT  = sm + OFF_SHT;
    float* sh2T = sm + OFF_SH2T;
    float* pp   = sm + OFF_PP;
    float* pp2  = sm + OFF_PP2;
    float* hpart= sm + OFF_HP;

    for (int idx = tid; idx < GPB * 75; idx += 256) {
        int g = idx / 75, kk = idx - g * 75;
        imgT[kk * 16 + g] = d_img[(g0 + g) * 75 + kk];
    }
    __syncthreads();

    // ---- stage 1: conv on 200 threads (1o x 4g) + emb on threads 200..255 ----
    if (tid < 200) {
        int o  = tid >> 2;              // 0..49
        int gb = (tid & 3) * 4;
        float acc[4];
        float b0 = sbc[o];
        acc[0] = b0; acc[1] = b0; acc[2] = b0; acc[3] = b0;
        const float* wr = &swc[o * 75];
        #pragma unroll 5
        for (int kk = 0; kk < 75; ++kk) {
            float wv = wr[kk];
            float4 v = *(const float4*)&imgT[kk * 16 + gb];
            acc[0] = fmaf(wv, v.x, acc[0]); acc[1] = fmaf(wv, v.y, acc[1]);
            acc[2] = fmaf(wv, v.z, acc[2]); acc[3] = fmaf(wv, v.w, acc[3]);
        }
        #pragma unroll
        for (int bb = 0; bb < 4; ++bb) shT[o * 16 + gb + bb] = tanha(acc[bb]);
    } else {
        int et = tid - 200;             // 0..55
        for (int task = et; task < 120; task += 56) {
            int q  = task >> 2;         // 0..29
            int gb = (task & 3) * 4;
            float be = sbe[q];
            float acc[4] = {be, be, be, be};
            #pragma unroll
            for (int p = 0; p < 6; ++p) {
                float wv = swe[p * 30 + q];
                acc[0] = fmaf(sprm[(gb + 0) * 9 + p], wv, acc[0]);
                acc[1] = fmaf(sprm[(gb + 1) * 9 + p], wv, acc[1]);
                acc[2] = fmaf(sprm[(gb + 2) * 9 + p], wv, acc[2]);
                acc[3] = fmaf(sprm[(gb + 3) * 9 + p], wv, acc[3]);
            }
            #pragma unroll
            for (int bb = 0; bb < 4; ++bb) shT[(50 + q) * 16 + gb + bb] = tanha(acc[bb]);
        }
    }
    __syncthreads();

    // ---- stage 2: 80x80 as 4q x 4g tiles, 3-way p split (240 threads) ----
    {
        const bool active = (tid < 240);
        int chunk = 0, q0 = 0, gb = 0, pst = 0, pen = 0;
        float acc[4][4];
        #pragma unroll
        for (int a = 0; a < 4; ++a)
            #pragma unroll
            for (int bb = 0; bb < 4; ++bb) acc[a][bb] = 0.0f;
        if (active) {
            chunk = tid / 80;            // 0,1,2
            int r = tid - chunk * 80;    // 0..79
            q0  = (r >> 2) * 4;          // 0..76
            gb  = (r & 3) * 4;           // 0,4,8,12
            pst = chunk * 27;
            pen = (chunk == 2) ? 80 : pst + 27;
            #pragma unroll 3
            for (int p = pst; p < pen; ++p) {
                float4 wv = *(const float4*)&swl[p * 80 + q0];
                float4 hv = *(const float4*)&shT[p * 16 + gb];
                acc[0][0] = fmaf(wv.x, hv.x, acc[0][0]); acc[0][1] = fmaf(wv.x, hv.y, acc[0][1]);
                acc[0][2] = fmaf(wv.x, hv.z, acc[0][2]); acc[0][3] = fmaf(wv.x, hv.w, acc[0][3]);
                acc[1][0] = fmaf(wv.y, hv.x, acc[1][0]); acc[1][1] = fmaf(wv.y, hv.y, acc[1][1]);
                acc[1][2] = fmaf(wv.y, hv.z, acc[1][2]); acc[1][3] = fmaf(wv.y, hv.w, acc[1][3]);
                acc[2][0] = fmaf(wv.z, hv.x, acc[2][0]); acc[2][1] = fmaf(wv.z, hv.y, acc[2][1]);
                acc[2][2] = fmaf(wv.z, hv.z, acc[2][2]); acc[2][3] = fmaf(wv.z, hv.w, acc[2][3]);
                acc[3][0] = fmaf(wv.w, hv.x, acc[3][0]); acc[3][1] = fmaf(wv.w, hv.y, acc[3][1]);
                acc[3][2] = fmaf(wv.w, hv.z, acc[3][2]); acc[3][3] = fmaf(wv.w, hv.w, acc[3][3]);
            }
        }
        if (active && chunk == 0) {
            #pragma unroll
            for (int a = 0; a < 4; ++a)
                #pragma unroll
                for (int bb = 0; bb < 4; ++bb)
                    pp[(q0 + a) * 16 + gb + bb] = acc[a][bb];
        }
        if (active && chunk == 1) {
            #pragma unroll
            for (int a = 0; a < 4; ++a)
                #pragma unroll
                for (int bb = 0; bb < 4; ++bb)
                    pp2[(q0 + a) * 16 + gb + bb] = acc[a][bb];
        }
        __syncthreads();                  // block-wide
        if (active && chunk == 2) {
            #pragma unroll
            for (int a = 0; a < 4; ++a) {
                float bl = sbl[q0 + a];
                #pragma unroll
                for (int bb = 0; bb < 4; ++bb)
                    sh2T[(q0 + a) * 16 + gb + bb] =
                        tanha(bl + acc[a][bb] + pp[(q0 + a) * 16 + gb + bb]
                                              + pp2[(q0 + a) * 16 + gb + bb]);
            }
        }
    }
    __syncthreads();

    // ---- stage 3: head, parallel over 4 p-chunks of 20 ----
    if (tid < od * 64) {
        int g = tid & 15;
        int r = tid >> 4;
        int d = r % od;
        int chunk = r / od;             // 0..3
        int pbase = chunk * 20;
        float acc = 0.0f;
        #pragma unroll 5
        for (int p = 0; p < 20; ++p)
            acc = fmaf(sh2T[(pbase + p) * 16 + g], shw[(pbase + p) * od + d], acc);
        hpart[(chunk * od + d) * 16 + g] = acc;
    }
    __syncthreads();
    if (tid < od * 16) {
        int g = tid & 15;
        int d = tid >> 4;
        float acc = shb[d];
        #pragma unroll
        for (int c = 0; c < 4; ++c) acc += hpart[(c * od + d) * 16 + g];
        int i = g0 + g;
        if      (m == 0) out[i * 6 + 0]     = sprm[g * 9 + 2]     + acc;
        else if (m == 1) out[i * 6 + 1 + d] = sprm[g * 9 + d]     + acc;
        else if (m == 2) out[i * 6 + 3 + d] = sprm[g * 9 + 3 + d] * __expf(acc);
        else             out[i * 6 + 5]     = sprm[g * 9 + 5]     + acc;
    }

    // ---- barrier counter reset (last block out restores initial state) ----
    __syncthreads();
    if (tid == 0) {
        unsigned d = atomicAdd(&g_depart, 1u) + 1u;
        if (d == GRID_TOTAL) { g_arrive = 0u; g_depart = 0u; __threadfence(); }
    }
}

// ---------------------------------------------------------------------------
extern "C" void kernel_launch(void* const* d_in, const int* in_sizes, int n_in,
                              void* d_out, int out_size)
{
    const float* means     = (const float*)d_in[0];
    const float* u         = (const float*)d_in[1];
    const float* scaling   = (const float*)d_in[2];
    const float* transform = (const float*)d_in[3];
    const float* conv_w    = (const float*)d_in[4];
    const float* conv_b    = (const float*)d_in[5];
    const float* emb_w     = (const float*)d_in[6];
    const float* emb_b     = (const float*)d_in[7];
    const float* lin1_w    = (const float*)d_in[8];
    const float* lin1_b    = (const float*)d_in[9];
    const float* sol_w     = (const float*)d_in[10];
    const float* sol_b     = (const float*)d_in[11];
    const float* tr_w      = (const float*)d_in[12];
    const float* tr_b      = (const float*)d_in[13];
    const float* sc_w      = (const float*)d_in[14];
    const float* sc_b      = (const float*)d_in[15];
    const float* tf_w      = (const float*)d_in[16];
    const float* tf_b      = (const float*)d_in[17];
    float* out             = (float*)d_out;

    static int smem_set = 0;
    if (!smem_set) {
        cudaFuncSetAttribute(k_all, cudaFuncAttributeMaxDynamicSharedMemorySize,
                             SMEM_FLTS * (int)sizeof(float));
        smem_set = 1;
    }

    k_all<<<GRID_TOTAL, 256, SMEM_FLTS * sizeof(float)>>>(
        means, u, scaling, transform,
        conv_w, conv_b, emb_w, emb_b, lin1_w, lin1_b,
        sol_w, sol_b, tr_w, tr_b, sc_w, sc_b, tf_w, tf_b, out);
}